// round 11
// baseline (speedup 1.0000x reference)
#include <cuda_runtime.h>
#include <cuda_fp16.h>
#include <cstdint>

// GATSingleLayer: N=50000, E=1e6, F_IN=256, HEADS=8, F_HEAD=32
#define NN      50000
#define NE      1000000
#define FIN     256
#define HEADS   8
#define FHEAD   32
#define FOUT    256
#define NEG_SLOPE 0.2f
#define NBLK    196              // ceil(NN/256)
#define KC      32               // K chunk
#define NCH     (FIN / KC)       // 8 chunks
#define PA      72               // As pitch (72 mod 32 = 8 -> conflict-free frags)
#define PB      136              // Bs pitch (136 mod 32 = 8)

// ---------------- device scratch ----------------
__device__ __align__(16) __half g_hh[(size_t)NN * FOUT]; // 25.6 MB fp16 messages
__device__ __align__(16) float g_asrc[NN * HEADS];
__device__ __align__(16) float g_adst[NN * HEADS];
__device__ int g_cnt[NN];
__device__ int g_off[NN + 1];
__device__ int g_cur[NN];
__device__ int g_sorted[NE];
__device__ int g_blk[NBLK];
__device__ int g_blkoff[NBLK];

// ---------------- helpers ----------------
__device__ __forceinline__ uint32_t tf32r(float x) {
    uint32_t u;
    asm("cvt.rna.tf32.f32 %0, %1;" : "=r"(u) : "f"(x));
    return u;
}
__device__ __forceinline__ void mma8(float* d, const uint32_t* a, uint32_t b0, uint32_t b1) {
    asm volatile("mma.sync.aligned.m16n8k8.row.col.f32.tf32.tf32.f32 "
                 "{%0,%1,%2,%3}, {%4,%5,%6,%7}, {%8,%9}, {%0,%1,%2,%3};"
                 : "+f"(d[0]), "+f"(d[1]), "+f"(d[2]), "+f"(d[3])
                 : "r"(a[0]), "r"(a[1]), "r"(a[2]), "r"(a[3]), "r"(b0), "r"(b1));
}

// ---------------- K0: zero histogram ----------------
__global__ void k_zero() {
    int i = blockIdx.x * blockDim.x + threadIdx.x;
    if (i < NN) g_cnt[i] = 0;
}

// ---------------- K1: tf32 mma.sync GEMM, tile 64x128, 2 CTAs/SM ----------------
__global__ __launch_bounds__(256, 2) void k_gemm(const float* __restrict__ X,
                                                 const float* __restrict__ W,
                                                 const float* __restrict__ att_src,
                                                 const float* __restrict__ att_dst) {
    __shared__ __align__(16) float As[KC][PA];    // [k][m], 64 rows used
    __shared__ __align__(16) float Bs[KC][PB];    // [k][n], 128 cols used
    __shared__ float s_as[128], s_ad[128];

    const int tid  = threadIdx.x;
    const int wid  = tid >> 5;
    const int lane = tid & 31;
    const int f0   = blockIdx.x * 128;
    const int m0   = blockIdx.y * 64;

    if (tid < 128) {
        s_as[tid] = att_src[f0 + tid];
        s_ad[tid] = att_dst[f0 + tid];
    }

    const int warp_m = wid & 1;           // 0..1 -> 32-row slice
    const int warp_n = wid >> 1;          // 0..3 -> 32-col slice (one head)
    const int mb = warp_m * 32;
    const int nb = warp_n * 32;
    const int lr = lane >> 2;             // 0..7
    const int lc = lane & 3;              // 0..3

    // A loader: row = tid&63, 8 consecutive k at ks = (tid>>6)*8
    const int rowA = tid & 63;
    const int ksA  = (tid >> 6) * 8;
    const bool aval = (m0 + rowA) < NN;
    const float* Aptr = X + (size_t)(m0 + rowA) * FIN + ksA;

    // B loader: k = tid>>3, 16 consecutive n at nq = (tid&7)*16
    const int kB = tid >> 3;
    const int nqB = (tid & 7) * 16;
    const float* Bptr = W + (size_t)kB * FOUT + f0 + nqB;

    float acc[2][4][4];                   // [wm][wn][frag]
    #pragma unroll
    for (int i = 0; i < 2; i++)
        #pragma unroll
        for (int j = 0; j < 4; j++)
            #pragma unroll
            for (int q = 0; q < 4; q++) acc[i][j][q] = 0.0f;

    float4 pa[2], pb[4];
    pa[0] = aval ? *(const float4*)(Aptr)     : make_float4(0.f, 0.f, 0.f, 0.f);
    pa[1] = aval ? *(const float4*)(Aptr + 4) : make_float4(0.f, 0.f, 0.f, 0.f);
    #pragma unroll
    for (int j = 0; j < 4; j++) pb[j] = *(const float4*)(Bptr + j * 4);

    for (int kt = 0; kt < NCH; kt++) {
        // commit prefetched chunk to smem (A transposed)
        As[ksA + 0][rowA] = pa[0].x;
        As[ksA + 1][rowA] = pa[0].y;
        As[ksA + 2][rowA] = pa[0].z;
        As[ksA + 3][rowA] = pa[0].w;
        As[ksA + 4][rowA] = pa[1].x;
        As[ksA + 5][rowA] = pa[1].y;
        As[ksA + 6][rowA] = pa[1].z;
        As[ksA + 7][rowA] = pa[1].w;
        #pragma unroll
        for (int j = 0; j < 4; j++) *(float4*)&Bs[kB][nqB + j * 4] = pb[j];
        __syncthreads();

        // prefetch next chunk
        if (kt + 1 < NCH) {
            const float* ap = Aptr + (kt + 1) * KC;
            pa[0] = aval ? *(const float4*)(ap)     : make_float4(0.f, 0.f, 0.f, 0.f);
            pa[1] = aval ? *(const float4*)(ap + 4) : make_float4(0.f, 0.f, 0.f, 0.f);
            const float* bp = Bptr + (size_t)(kt + 1) * KC * FOUT;
            #pragma unroll
            for (int j = 0; j < 4; j++) pb[j] = *(const float4*)(bp + j * 4);
        }

        #pragma unroll
        for (int k8 = 0; k8 < KC / 8; k8++) {
            const int kb = k8 * 8;
            uint32_t ahi[2][4], alo[2][4];
            #pragma unroll
            for (int wm = 0; wm < 2; wm++) {
                int r = mb + wm * 16 + lr;
                float a0 = As[kb + lc][r];
                float a1 = As[kb + lc][r + 8];
                float a2 = As[kb + lc + 4][r];
                float a3 = As[kb + lc + 4][r + 8];
                ahi[wm][0] = tf32r(a0); alo[wm][0] = __float_as_uint(a0 - __uint_as_float(ahi[wm][0]));
                ahi[wm][1] = tf32r(a1); alo[wm][1] = __float_as_uint(a1 - __uint_as_float(ahi[wm][1]));
                ahi[wm][2] = tf32r(a2); alo[wm][2] = __float_as_uint(a2 - __uint_as_float(ahi[wm][2]));
                ahi[wm][3] = tf32r(a3); alo[wm][3] = __float_as_uint(a3 - __uint_as_float(ahi[wm][3]));
            }
            #pragma unroll
            for (int wn = 0; wn < 4; wn++) {
                int bc = nb + wn * 8 + lr;
                float b0 = Bs[kb + lc][bc];
                float b1 = Bs[kb + lc + 4][bc];
                uint32_t bh0 = tf32r(b0), bh1 = tf32r(b1);
                uint32_t bl0 = __float_as_uint(b0 - __uint_as_float(bh0));
                uint32_t bl1 = __float_as_uint(b1 - __uint_as_float(bh1));
                #pragma unroll
                for (int wm = 0; wm < 2; wm++) {
                    mma8(acc[wm][wn], ahi[wm], bh0, bh1);
                    mma8(acc[wm][wn], alo[wm], bh0, bh1);
                    mma8(acc[wm][wn], ahi[wm], bl0, bl1);
                }
            }
        }
        __syncthreads();
    }

    // ---- epilogue: h store (fp16) + fused a_src/a_dst (one head per warp) ----
    // acc frag: d0=(lr, 2lc), d1=(lr, 2lc+1), d2=(lr+8, 2lc), d3=(lr+8, 2lc+1)
    const int head = (f0 + nb) >> 5;
    #pragma unroll
    for (int wm = 0; wm < 2; wm++) {
        #pragma unroll
        for (int half = 0; half < 2; half++) {
            int m = m0 + mb + wm * 16 + half * 8 + lr;
            bool mval = m < NN;
            if (mval) {
                __half* hp = g_hh + (size_t)m * FOUT + f0 + nb + lc * 2;
                #pragma unroll
                for (int wn = 0; wn < 4; wn++) {
                    __half2 hv = __floats2half2_rn(acc[wm][wn][2 * half],
                                                   acc[wm][wn][2 * half + 1]);
                    *(__half2*)(hp + wn * 8) = hv;
                }
            }
            float ps = 0.f, pd = 0.f;
            #pragma unroll
            for (int wn = 0; wn < 4; wn++) {
                int cl = nb + wn * 8 + lc * 2;
                float v0 = acc[wm][wn][2 * half];
                float v1 = acc[wm][wn][2 * half + 1];
                ps += v0 * s_as[cl] + v1 * s_as[cl + 1];
                pd += v0 * s_ad[cl] + v1 * s_ad[cl + 1];
            }
            #pragma unroll
            for (int off = 1; off < 4; off <<= 1) {
                ps += __shfl_xor_sync(0xffffffffu, ps, off);
                pd += __shfl_xor_sync(0xffffffffu, pd, off);
            }
            if (lc == 0 && mval) {
                g_asrc[m * HEADS + head] = ps;
                g_adst[m * HEADS + head] = pd;
            }
        }
    }
}

// ---------------- K2: degree histogram ----------------
__global__ __launch_bounds__(256) void k_hist(const int* __restrict__ ei) {
    int e = blockIdx.x * blockDim.x + threadIdx.x;
    if (e < NE) atomicAdd(&g_cnt[ei[NE + e]], 1);
}

// ---------------- K3a/b/c: multi-block scan ----------------
__global__ __launch_bounds__(256) void k_scan1() {
    __shared__ int sp[256];
    int b = blockIdx.x, t = threadIdx.x;
    int idx = b * 256 + t;
    int v = (idx < NN) ? g_cnt[idx] : 0;
    sp[t] = v;
    __syncthreads();
    #pragma unroll
    for (int off = 1; off < 256; off <<= 1) {
        int u = (t >= off) ? sp[t - off] : 0;
        __syncthreads();
        sp[t] += u;
        __syncthreads();
    }
    if (idx < NN) g_off[idx] = sp[t] - v;
    if (t == 255) g_blk[b] = sp[255];
}
__global__ __launch_bounds__(256) void k_scan2() {
    __shared__ int sp[256];
    int t = threadIdx.x;
    int v = (t < NBLK) ? g_blk[t] : 0;
    sp[t] = v;
    __syncthreads();
    #pragma unroll
    for (int off = 1; off < 256; off <<= 1) {
        int u = (t >= off) ? sp[t - off] : 0;
        __syncthreads();
        sp[t] += u;
        __syncthreads();
    }
    if (t < NBLK) g_blkoff[t] = sp[t] - v;
}
__global__ __launch_bounds__(256) void k_scan3() {
    int idx = blockIdx.x * blockDim.x + threadIdx.x;
    if (idx < NN) {
        int o = g_off[idx] + g_blkoff[idx >> 8];
        g_off[idx] = o;
        g_cur[idx] = o;
    }
    if (idx == 0) g_off[NN] = NE;
}

// ---------------- K4: scatter ----------------
__global__ __launch_bounds__(256) void k_scatter(const int* __restrict__ ei) {
    int e = blockIdx.x * blockDim.x + threadIdx.x;
    if (e >= NE) return;
    int src = ei[e];
    int dst = ei[NE + e];
    int p = atomicAdd(&g_cur[dst], 1);
    g_sorted[p] = src;
}

// ---------------- K5: per-node softmax + weighted aggregation (warp per node) ------
__global__ __launch_bounds__(256) void k_node(const float* __restrict__ bias,
                                              float* __restrict__ out) {
    int n = (blockIdx.x * blockDim.x + threadIdx.x) >> 5;
    if (n >= NN) return;
    int lane = threadIdx.x & 31;

    int s0 = g_off[n];
    int s1 = g_off[n + 1];

    float ad = g_adst[n * HEADS + (lane & 7)];

    float den = 0.0f;
    for (int e = s0; e < s1; e++) {
        int s = g_sorted[e];
        float v = g_asrc[s * HEADS + (lane & 7)] + ad;
        v = (v > 0.0f) ? v : NEG_SLOPE * v;
        den += __expf(v);
    }
    float rden = (den > 0.0f) ? (1.0f / den) : 0.0f;

    float acc[8];
    #pragma unroll
    for (int j = 0; j < 8; j++) acc[j] = 0.0f;

    for (int e = s0; e < s1; e++) {
        int s = g_sorted[e];
        float v = g_asrc[s * HEADS + (lane & 7)] + ad;
        v = (v > 0.0f) ? v : NEG_SLOPE * v;
        float al = __expf(v) * rden;
        float a = __shfl_sync(0xffffffffu, al, lane >> 2);   // head for my 8 cols
        uint4 hv = *(const uint4*)(g_hh + (size_t)s * FOUT + lane * 8);
        const __half2* hp = (const __half2*)&hv;
        #pragma unroll
        for (int j = 0; j < 4; j++) {
            float2 f = __half22float2(hp[j]);
            acc[2 * j]     += a * f.x;
            acc[2 * j + 1] += a * f.y;
        }
    }

    const float* bp = bias + lane * 8;
    float* op = out + (size_t)n * FOUT + lane * 8;
    float4 o0 = make_float4(acc[0] + bp[0], acc[1] + bp[1], acc[2] + bp[2], acc[3] + bp[3]);
    float4 o1 = make_float4(acc[4] + bp[4], acc[5] + bp[5], acc[6] + bp[6], acc[7] + bp[7]);
    *(float4*)(op)     = o0;
    *(float4*)(op + 4) = o1;
}

// ---------------- launch ----------------
extern "C" void kernel_launch(void* const* d_in, const int* in_sizes, int n_in,
                              void* d_out, int out_size) {
    const float* x       = (const float*)d_in[0];
    const float* W       = (const float*)d_in[1];
    const float* att_src = (const float*)d_in[2];
    const float* att_dst = (const float*)d_in[3];
    const float* bias    = (const float*)d_in[4];
    const int*   ei      = (const int*)d_in[5];
    float*       out     = (float*)d_out;

    int eb = (NE + 255) / 256;

    k_zero<<<(NN + 255) / 256, 256>>>();          // 1
    k_hist<<<eb, 256>>>(ei);                      // 2
    k_scan1<<<NBLK, 256>>>();                     // 3

    dim3 ggrid(FOUT / 128, (NN + 63) / 64);       // (2, 782)
    k_gemm<<<ggrid, 256>>>(x, W, att_src, att_dst);  // 4  <- profiled slot

    k_scan2<<<1, 256>>>();                        // 5
    k_scan3<<<NBLK, 256>>>();                     // 6
    k_scatter<<<eb, 256>>>(ei);                   // 7
    k_node<<<(NN * 32 + 255) / 256, 256>>>(bias, out);  // 8
}

// round 12
// speedup vs baseline: 1.0902x; 1.0902x over previous
#include <cuda_runtime.h>
#include <cuda_fp16.h>
#include <cstdint>

// GATSingleLayer: N=50000, E=1e6, F_IN=256, HEADS=8, F_HEAD=32
#define NN      50000
#define NE      1000000
#define FIN     256
#define HEADS   8
#define FHEAD   32
#define FOUT    256
#define NEG_SLOPE 0.2f
#define NBLK    196              // ceil(NN/256)
#define KC      16               // K chunk
#define NCH     (FIN / KC)       // 16 chunks
#define PAK     20               // A smem pitch over k (floats): banks (20r+c)%32 distinct
#define PBN     132              // B smem pitch over n (floats): banks (4k+n)%32 distinct

// ---------------- device scratch ----------------
__device__ __align__(16) __half g_hh[(size_t)NN * FOUT]; // 25.6 MB fp16 messages
__device__ __align__(16) float g_asrc[NN * HEADS];
__device__ __align__(16) float g_adst[NN * HEADS];
__device__ int g_cnt[NN];
__device__ int g_off[NN + 1];
__device__ int g_cur[NN];
__device__ int g_sorted[NE];
__device__ int g_blk[NBLK];
__device__ int g_blkoff[NBLK];

// ---------------- helpers ----------------
__device__ __forceinline__ uint32_t smem_u32(const void* p) {
    uint32_t a;
    asm("{ .reg .u64 t; cvta.to.shared.u64 t, %1; cvt.u32.u64 %0, t; }" : "=r"(a) : "l"(p));
    return a;
}
__device__ __forceinline__ void cpa16(uint32_t dst, const void* src, int szvalid) {
    asm volatile("cp.async.cg.shared.global [%0], [%1], 16, %2;"
                 :: "r"(dst), "l"(src), "r"(szvalid) : "memory");
}
__device__ __forceinline__ uint32_t tf32r(float x) {
    uint32_t u;
    asm("cvt.rna.tf32.f32 %0, %1;" : "=r"(u) : "f"(x));
    return u;
}
__device__ __forceinline__ void mma8(float* d, const uint32_t* a, uint32_t b0, uint32_t b1) {
    asm volatile("mma.sync.aligned.m16n8k8.row.col.f32.tf32.tf32.f32 "
                 "{%0,%1,%2,%3}, {%4,%5,%6,%7}, {%8,%9}, {%0,%1,%2,%3};"
                 : "+f"(d[0]), "+f"(d[1]), "+f"(d[2]), "+f"(d[3])
                 : "r"(a[0]), "r"(a[1]), "r"(a[2]), "r"(a[3]), "r"(b0), "r"(b1));
}

// ---------------- K0: zero histogram ----------------
__global__ void k_zero() {
    int i = blockIdx.x * blockDim.x + threadIdx.x;
    if (i < NN) g_cnt[i] = 0;
}

// ---------------- K1: tf32 mma.sync GEMM, 128x128 tile, cp.async, 2 CTAs/SM --------
__global__ __launch_bounds__(256, 2) void k_gemm(const float* __restrict__ X,
                                                 const float* __restrict__ W,
                                                 const float* __restrict__ att_src,
                                                 const float* __restrict__ att_dst) {
    __shared__ __align__(16) float As[2][128][PAK];   // [buf][m][k]
    __shared__ __align__(16) float Bs[2][KC][PBN];    // [buf][k][n]
    __shared__ float s_as[128], s_ad[128];

    const int tid  = threadIdx.x;
    const int wid  = tid >> 5;
    const int lane = tid & 31;
    const int f0   = blockIdx.x * 128;
    const int m0   = blockIdx.y * 128;

    if (tid < 128) {
        s_as[tid] = att_src[f0 + tid];
        s_ad[tid] = att_dst[f0 + tid];
    }

    const int warp_m = wid & 3;           // 0..3 -> 32-row slice
    const int warp_n = wid >> 2;          // 0..1 -> 64-col slice (2 heads)
    const int mb = warp_m * 32;
    const int nb = warp_n * 64;
    const int lr = lane >> 2;             // 0..7
    const int lc = lane & 3;              // 0..3

    // async loaders: 2 x 16B per thread per operand per chunk
    // A: idx = tid + 256j -> row = idx>>2 (0..127), q = idx&3 (float4 within 16 k)
    const int rA = tid >> 2;
    const int qA = tid & 3;
    // B: idx = tid + 256j -> k = idx>>5 (0..15), nq = idx&31
    const int kB = tid >> 5;
    const int nqB = tid & 31;

    float acc[2][8][4];
    #pragma unroll
    for (int i = 0; i < 2; i++)
        #pragma unroll
        for (int j = 0; j < 8; j++)
            #pragma unroll
            for (int q = 0; q < 4; q++) acc[i][j][q] = 0.0f;

    // chunk loader (cp.async)
    auto load_chunk = [&](int kt, int buf) {
        #pragma unroll
        for (int j = 0; j < 2; j++) {
            int r = rA + 64 * j;
            int valid = (m0 + r) < NN ? 16 : 0;
            cpa16(smem_u32(&As[buf][r][qA * 4]),
                  X + (size_t)(m0 + r) * FIN + kt * KC + qA * 4, valid);
        }
        #pragma unroll
        for (int j = 0; j < 2; j++) {
            int k = kB + 8 * j;
            cpa16(smem_u32(&Bs[buf][k][nqB * 4]),
                  W + (size_t)(kt * KC + k) * FOUT + f0 + nqB * 4, 16);
        }
    };

    load_chunk(0, 0);
    asm volatile("cp.async.commit_group;" ::: "memory");

    int buf = 0;
    for (int kt = 0; kt < NCH; kt++) {
        if (kt + 1 < NCH) {
            load_chunk(kt + 1, buf ^ 1);
            asm volatile("cp.async.commit_group;" ::: "memory");
            asm volatile("cp.async.wait_group 1;" ::: "memory");
        } else {
            asm volatile("cp.async.wait_group 0;" ::: "memory");
        }
        __syncthreads();

        #pragma unroll
        for (int k8 = 0; k8 < KC / 8; k8++) {
            const int kb = k8 * 8;
            uint32_t ahi[2][4], alo[2][4];
            #pragma unroll
            for (int wm = 0; wm < 2; wm++) {
                int r = mb + wm * 16 + lr;
                float a0 = As[buf][r][kb + lc];
                float a1 = As[buf][r + 8][kb + lc];
                float a2 = As[buf][r][kb + lc + 4];
                float a3 = As[buf][r + 8][kb + lc + 4];
                ahi[wm][0] = tf32r(a0); alo[wm][0] = __float_as_uint(a0 - __uint_as_float(ahi[wm][0]));
                ahi[wm][1] = tf32r(a1); alo[wm][1] = __float_as_uint(a1 - __uint_as_float(ahi[wm][1]));
                ahi[wm][2] = tf32r(a2); alo[wm][2] = __float_as_uint(a2 - __uint_as_float(ahi[wm][2]));
                ahi[wm][3] = tf32r(a3); alo[wm][3] = __float_as_uint(a3 - __uint_as_float(ahi[wm][3]));
            }
            #pragma unroll
            for (int wn = 0; wn < 8; wn++) {
                int bc = nb + wn * 8 + lr;
                float b0 = Bs[buf][kb + lc][bc];
                float b1 = Bs[buf][kb + lc + 4][bc];
                uint32_t bh0 = tf32r(b0), bh1 = tf32r(b1);
                uint32_t bl0 = __float_as_uint(b0 - __uint_as_float(bh0));
                uint32_t bl1 = __float_as_uint(b1 - __uint_as_float(bh1));
                #pragma unroll
                for (int wm = 0; wm < 2; wm++) {
                    mma8(acc[wm][wn], ahi[wm], bh0, bh1);
                    mma8(acc[wm][wn], alo[wm], bh0, bh1);
                    mma8(acc[wm][wn], ahi[wm], bl0, bl1);
                }
            }
        }
        __syncthreads();
        buf ^= 1;
    }

    // ---- epilogue: h store (fp16) + fused a_src/a_dst ----
    // acc frag: d0=(lr, 2lc), d1=(lr, 2lc+1), d2=(lr+8, 2lc), d3=(lr+8, 2lc+1)
    #pragma unroll
    for (int wm = 0; wm < 2; wm++) {
        #pragma unroll
        for (int half = 0; half < 2; half++) {
            int m = m0 + mb + wm * 16 + half * 8 + lr;
            bool mval = m < NN;
            if (mval) {
                __half* hp = g_hh + (size_t)m * FOUT + f0 + nb + lc * 2;
                #pragma unroll
                for (int wn = 0; wn < 8; wn++) {
                    __half2 hv = __floats2half2_rn(acc[wm][wn][2 * half],
                                                   acc[wm][wn][2 * half + 1]);
                    *(__half2*)(hp + wn * 8) = hv;
                }
            }
            float psA = 0.f, pdA = 0.f, psB = 0.f, pdB = 0.f;
            #pragma unroll
            for (int wn = 0; wn < 8; wn++) {
                int col = nb + wn * 8 + lc * 2;
                float v0 = acc[wm][wn][2 * half];
                float v1 = acc[wm][wn][2 * half + 1];
                float s = v0 * s_as[col] + v1 * s_as[col + 1];
                float d = v0 * s_ad[col] + v1 * s_ad[col + 1];
                if (wn < 4) { psA += s; pdA += d; }
                else        { psB += s; pdB += d; }
            }
            #pragma unroll
            for (int off = 1; off < 4; off <<= 1) {
                psA += __shfl_xor_sync(0xffffffffu, psA, off);
                pdA += __shfl_xor_sync(0xffffffffu, pdA, off);
                psB += __shfl_xor_sync(0xffffffffu, psB, off);
                pdB += __shfl_xor_sync(0xffffffffu, pdB, off);
            }
            if (lc == 0 && mval) {
                int headA = ((f0 + nb) >> 5);
                g_asrc[m * HEADS + headA]     = psA;
                g_adst[m * HEADS + headA]     = pdA;
                g_asrc[m * HEADS + headA + 1] = psB;
                g_adst[m * HEADS + headA + 1] = pdB;
            }
        }
    }
}

// ---------------- K2: degree histogram ----------------
__global__ __launch_bounds__(256) void k_hist(const int* __restrict__ ei) {
    int e = blockIdx.x * blockDim.x + threadIdx.x;
    if (e < NE) atomicAdd(&g_cnt[ei[NE + e]], 1);
}

// ---------------- K3a/b/c: multi-block scan ----------------
__global__ __launch_bounds__(256) void k_scan1() {
    __shared__ int sp[256];
    int b = blockIdx.x, t = threadIdx.x;
    int idx = b * 256 + t;
    int v = (idx < NN) ? g_cnt[idx] : 0;
    sp[t] = v;
    __syncthreads();
    #pragma unroll
    for (int off = 1; off < 256; off <<= 1) {
        int u = (t >= off) ? sp[t - off] : 0;
        __syncthreads();
        sp[t] += u;
        __syncthreads();
    }
    if (idx < NN) g_off[idx] = sp[t] - v;
    if (t == 255) g_blk[b] = sp[255];
}
__global__ __launch_bounds__(256) void k_scan2() {
    __shared__ int sp[256];
    int t = threadIdx.x;
    int v = (t < NBLK) ? g_blk[t] : 0;
    sp[t] = v;
    __syncthreads();
    #pragma unroll
    for (int off = 1; off < 256; off <<= 1) {
        int u = (t >= off) ? sp[t - off] : 0;
        __syncthreads();
        sp[t] += u;
        __syncthreads();
    }
    if (t < NBLK) g_blkoff[t] = sp[t] - v;
}
__global__ __launch_bounds__(256) void k_scan3() {
    int idx = blockIdx.x * blockDim.x + threadIdx.x;
    if (idx < NN) {
        int o = g_off[idx] + g_blkoff[idx >> 8];
        g_off[idx] = o;
        g_cur[idx] = o;
    }
    if (idx == 0) g_off[NN] = NE;
}

// ---------------- K4: scatter ----------------
__global__ __launch_bounds__(256) void k_scatter(const int* __restrict__ ei) {
    int e = blockIdx.x * blockDim.x + threadIdx.x;
    if (e >= NE) return;
    int src = ei[e];
    int dst = ei[NE + e];
    int p = atomicAdd(&g_cur[dst], 1);
    g_sorted[p] = src;
}

// ---------------- K5: per-node softmax + weighted aggregation (warp per node) ------
__global__ __launch_bounds__(256) void k_node(const float* __restrict__ bias,
                                              float* __restrict__ out) {
    int n = (blockIdx.x * blockDim.x + threadIdx.x) >> 5;
    if (n >= NN) return;
    int lane = threadIdx.x & 31;

    int s0 = g_off[n];
    int s1 = g_off[n + 1];

    float ad = g_adst[n * HEADS + (lane & 7)];

    float den = 0.0f;
    for (int e = s0; e < s1; e++) {
        int s = g_sorted[e];
        float v = g_asrc[s * HEADS + (lane & 7)] + ad;
        v = (v > 0.0f) ? v : NEG_SLOPE * v;
        den += __expf(v);
    }
    float rden = (den > 0.0f) ? (1.0f / den) : 0.0f;

    float acc[8];
    #pragma unroll
    for (int j = 0; j < 8; j++) acc[j] = 0.0f;

    for (int e = s0; e < s1; e++) {
        int s = g_sorted[e];
        float v = g_asrc[s * HEADS + (lane & 7)] + ad;
        v = (v > 0.0f) ? v : NEG_SLOPE * v;
        float al = __expf(v) * rden;
        float a = __shfl_sync(0xffffffffu, al, lane >> 2);   // head for my 8 cols
        uint4 hv = *(const uint4*)(g_hh + (size_t)s * FOUT + lane * 8);
        const __half2* hp = (const __half2*)&hv;
        #pragma unroll
        for (int j = 0; j < 4; j++) {
            float2 f = __half22float2(hp[j]);
            acc[2 * j]     += a * f.x;
            acc[2 * j + 1] += a * f.y;
        }
    }

    const float* bp = bias + lane * 8;
    float* op = out + (size_t)n * FOUT + lane * 8;
    float4 o0 = make_float4(acc[0] + bp[0], acc[1] + bp[1], acc[2] + bp[2], acc[3] + bp[3]);
    float4 o1 = make_float4(acc[4] + bp[4], acc[5] + bp[5], acc[6] + bp[6], acc[7] + bp[7]);
    *(float4*)(op)     = o0;
    *(float4*)(op + 4) = o1;
}

// ---------------- launch ----------------
extern "C" void kernel_launch(void* const* d_in, const int* in_sizes, int n_in,
                              void* d_out, int out_size) {
    const float* x       = (const float*)d_in[0];
    const float* W       = (const float*)d_in[1];
    const float* att_src = (const float*)d_in[2];
    const float* att_dst = (const float*)d_in[3];
    const float* bias    = (const float*)d_in[4];
    const int*   ei      = (const int*)d_in[5];
    float*       out     = (float*)d_out;

    int eb = (NE + 255) / 256;

    k_zero<<<(NN + 255) / 256, 256>>>();          // 1
    k_hist<<<eb, 256>>>(ei);                      // 2
    k_scan1<<<NBLK, 256>>>();                     // 3

    dim3 ggrid(FOUT / 128, (NN + 127) / 128);     // (2, 391)
    k_gemm<<<ggrid, 256>>>(x, W, att_src, att_dst);  // 4  <- profiled slot

    k_scan2<<<1, 256>>>();                        // 5
    k_scan3<<<NBLK, 256>>>();                     // 6
    k_scatter<<<eb, 256>>>(ei);                   // 7
    k_node<<<(NN * 32 + 255) / 256, 256>>>(bias, out);  // 8
}